// round 5
// baseline (speedup 1.0000x reference)
#include <cuda_runtime.h>

// ---------------------------------------------------------------------------
// PrecisionPredictorLoss — single fused kernel, register-budget aware.
//   eff  = mean((P - T)^2)                 over B*d*d elements
//   tr_p[b], tr_t[b] = trace of first m=min(B,32) matrices (d=64)
//   rank = sum_{i<j} margin(tr) / (m*(m-1)/2)
//   total = eff + 0.1 * rank
// Shapes fixed by problem: B=4096, d=64.
//
// 592 streaming blocks (4/SM -> 64-reg budget, unroll 8 => 16 LDG.128 in
// flight/thread) + 1 trace block. Last block via integer ticket performs the
// finalize on L2-hot partials, then resets the ticket (graph-replay safe).
// ---------------------------------------------------------------------------

#define NBLK 592           // 148 SMs * 4 streaming blocks
#define TPB  256
#define NTOT (NBLK + 1)

__device__ float g_partials[NBLK];
__device__ float g_tr_p[32];
__device__ float g_tr_t[32];
__device__ unsigned int g_ticket = 0;   // statically zero; reset each run

__device__ __forceinline__ float warp_sum(float v) {
    #pragma unroll
    for (int o = 16; o; o >>= 1) v += __shfl_down_sync(0xffffffffu, v, o);
    return v;
}

__global__ void __launch_bounds__(TPB, 4) fused_loss(
    const float4* __restrict__ p, const float4* __restrict__ t,
    float* __restrict__ out, int n4, int B, long long n_total, int out_size)
{
    __shared__ float s[TPB / 32];
    __shared__ bool s_last;

    const int tid  = threadIdx.x;
    const int warp = tid >> 5;
    const int lane = tid & 31;
    const int m    = (B < 32) ? B : 32;

    if (blockIdx.x == NBLK) {
        // ---- trace block: 8 warps x 4 matrices each ----
        const float* pf = (const float*)p;
        const float* tf = (const float*)t;
        #pragma unroll
        for (int k = 0; k < 4; k++) {
            int b = warp * 4 + k;
            if (b >= m) break;
            const long long base = (long long)b * 64 * 64;
            float tp = pf[base + (long long)lane * 65]
                     + pf[base + (long long)(lane + 32) * 65];
            float tt = tf[base + (long long)lane * 65]
                     + tf[base + (long long)(lane + 32) * 65];
            tp = warp_sum(tp);
            tt = warp_sum(tt);
            if (lane == 0) { g_tr_p[b] = tp; g_tr_t[b] = tt; }
        }
    } else {
        // ---- streaming squared-diff partial reduction (deep unroll) ----
        float acc = 0.0f;
        const int stride = NBLK * TPB;
        int i = blockIdx.x * TPB + tid;
        #pragma unroll 8
        for (; i < n4; i += stride) {
            float4 a = p[i];
            float4 b = t[i];
            float d0 = a.x - b.x, d1 = a.y - b.y, d2 = a.z - b.z, d3 = a.w - b.w;
            acc = fmaf(d0, d0, acc);
            acc = fmaf(d1, d1, acc);
            acc = fmaf(d2, d2, acc);
            acc = fmaf(d3, d3, acc);
        }
        acc = warp_sum(acc);
        if (lane == 0) s[warp] = acc;
        __syncthreads();
        if (tid < 32) {
            float v = (tid < TPB / 32) ? s[tid] : 0.0f;
            #pragma unroll
            for (int o = 4; o; o >>= 1) v += __shfl_down_sync(0xffffffffu, v, o);
            if (tid == 0) g_partials[blockIdx.x] = v;
        }
    }

    // ---- ticket: last block to arrive performs the finalize ----
    __threadfence();
    if (tid == 0) {
        unsigned int ticket = atomicAdd(&g_ticket, 1u);
        s_last = (ticket == NTOT - 1);
    }
    __syncthreads();
    if (!s_last) return;

    // =========================== FINALIZE (one block) =======================
    // 1) reduce NBLK partials (L2-hot)
    float sum = 0.0f;
    for (int i = tid; i < NBLK; i += TPB) sum += g_partials[i];
    sum = warp_sum(sum);
    if (lane == 0) s[warp] = sum;
    __syncthreads();
    float sumsq = 0.0f;
    if (tid == 0) {
        #pragma unroll
        for (int i = 0; i < TPB / 32; i++) sumsq += s[i];
    }
    __syncthreads();   // s[] reuse below

    // 2) rank loss: 1024 (i,j) slots over 256 threads, 4 slots each
    float c = 0.0f;
    #pragma unroll
    for (int sIdx = 0; sIdx < 4; sIdx++) {
        int idx = tid + TPB * sIdx;     // 0..1023
        int i = idx >> 5;
        int j = idx & 31;
        if (i < j && j < m) {
            float dt = g_tr_t[i] - g_tr_t[j];
            float dp = g_tr_p[i] - g_tr_p[j];
            if (dt > 0.0f)      c += fmaxf(-dp + 0.1f, 0.0f);
            else if (dt < 0.0f) c += fmaxf( dp + 0.1f, 0.0f);
        }
    }
    c = warp_sum(c);
    if (lane == 0) s[warp] = c;
    __syncthreads();

    // 3) combine, write outputs, reset ticket for next graph replay
    if (tid == 0) {
        float rank_total = 0.0f;
        #pragma unroll
        for (int i = 0; i < TPB / 32; i++) rank_total += s[i];
        float eff = sumsq / (float)n_total;
        int n_pairs = m * (m - 1) / 2;
        float rank = (m > 1) ? (rank_total / (float)n_pairs) : 0.0f;
        out[0] = eff + 0.1f * rank;
        if (out_size > 1) out[1] = eff;
        if (out_size > 2) out[2] = rank;
        __threadfence();
        g_ticket = 0;                  // deterministic replay
    }
}

extern "C" void kernel_launch(void* const* d_in, const int* in_sizes, int n_in,
                              void* d_out, int out_size)
{
    const float* pred = (const float*)d_in[0];
    const float* tru  = (const float*)d_in[1];
    float* out = (float*)d_out;

    long long n = (long long)in_sizes[0];   // B * 64 * 64
    int n4 = (int)(n / 4);
    int B  = (int)(n / (64 * 64));

    fused_loss<<<NTOT, TPB>>>((const float4*)pred, (const float4*)tru,
                              out, n4, B, n, out_size);
}

// round 6
// speedup vs baseline: 1.0748x; 1.0748x over previous
#include <cuda_runtime.h>

// ---------------------------------------------------------------------------
// PrecisionPredictorLoss — single kernel, dedicated finalizer block.
//   eff  = mean((P - T)^2)                 over B*d*d elements
//   tr_p[b], tr_t[b] = trace of first m=min(B,32) matrices (d=64)
//   rank = sum_{i<j} margin(tr) / (m*(m-1)/2)
//   total = eff + 0.1 * rank
// Shapes fixed by problem: B=4096, d=64.
//
// Grid = 1184 = 148 SMs * 8 blocks (exactly one wave at <=32 regs).
//   block 0      : trace computation, then polls ticket, then finalize.
//   blocks 1..1183: streaming sq-diff partials; tid0 does ONE fence + ONE
//                   atomic per block (not per thread) and the block exits.
// Streaming blocks never wait on block 0 -> forward progress guaranteed.
// Block 0 resets the ticket -> deterministic under CUDA-graph replay.
// ---------------------------------------------------------------------------

#define NSTREAM 1183
#define TPB     256

__device__ float g_partials[NSTREAM];
__device__ unsigned int g_ticket = 0;   // statically zero; reset by block 0

__device__ __forceinline__ float warp_sum(float v) {
    #pragma unroll
    for (int o = 16; o; o >>= 1) v += __shfl_down_sync(0xffffffffu, v, o);
    return v;
}

__global__ void __launch_bounds__(TPB, 8) fused_loss(
    const float4* __restrict__ p, const float4* __restrict__ t,
    float* __restrict__ out, int n4, int B, long long n_total, int out_size)
{
    const int tid  = threadIdx.x;
    const int warp = tid >> 5;
    const int lane = tid & 31;

    if (blockIdx.x != 0) {
        // ================= streaming squared-diff partial =================
        __shared__ float s[TPB / 32];
        float acc = 0.0f;
        const int stride = NSTREAM * TPB;
        #pragma unroll 4
        for (int i = (int)(blockIdx.x - 1) * TPB + tid; i < n4; i += stride) {
            float4 a = __ldcs(&p[i]);
            float4 b = __ldcs(&t[i]);
            float d0 = a.x - b.x, d1 = a.y - b.y, d2 = a.z - b.z, d3 = a.w - b.w;
            acc = fmaf(d0, d0, acc);
            acc = fmaf(d1, d1, acc);
            acc = fmaf(d2, d2, acc);
            acc = fmaf(d3, d3, acc);
        }
        acc = warp_sum(acc);
        if (lane == 0) s[warp] = acc;
        __syncthreads();
        if (tid == 0) {
            float v = 0.0f;
            #pragma unroll
            for (int i = 0; i < TPB / 32; i++) v += s[i];
            g_partials[blockIdx.x - 1] = v;
            __threadfence();                    // one fence per block
            atomicAdd(&g_ticket, 1u);           // one atomic per block
        }
        return;
    }

    // ======================= block 0: finalizer =======================
    __shared__ float tr_p[32], tr_t[32];
    __shared__ float red[TPB / 32];
    const int m = (B < 32) ? B : 32;

    // ---- traces of first m matrices (overlaps with the streaming wave) ----
    {
        const float* pf = (const float*)p;
        const float* tf = (const float*)t;
        #pragma unroll
        for (int k = 0; k < 4; k++) {
            int b = warp * 4 + k;
            if (b < m) {
                const long long base = (long long)b * 64 * 64;
                float tp = pf[base + (long long)lane * 65]
                         + pf[base + (long long)(lane + 32) * 65];
                float tt = tf[base + (long long)lane * 65]
                         + tf[base + (long long)(lane + 32) * 65];
                tp = warp_sum(tp);
                tt = warp_sum(tt);
                if (lane == 0) { tr_p[b] = tp; tr_t[b] = tt; }
            }
        }
    }

    // ---- wait for all streaming partials ----
    if (tid == 0) {
        volatile unsigned int* tk = &g_ticket;
        while (*tk != NSTREAM) __nanosleep(128);
        __threadfence();   // acquire: make partials visible
    }
    __syncthreads();

    // ---- reduce the NSTREAM partials (L2-hot) ----
    float sum = 0.0f;
    for (int i = tid; i < NSTREAM; i += TPB) sum += g_partials[i];
    sum = warp_sum(sum);
    if (lane == 0) red[warp] = sum;
    __syncthreads();
    float sumsq = 0.0f;
    if (tid == 0) {
        #pragma unroll
        for (int i = 0; i < TPB / 32; i++) sumsq += red[i];
    }
    __syncthreads();   // red[] reuse below

    // ---- rank loss: 1024 (i,j) slots over 256 threads ----
    float c = 0.0f;
    #pragma unroll
    for (int sIdx = 0; sIdx < 4; sIdx++) {
        int idx = tid + TPB * sIdx;     // 0..1023
        int i = idx >> 5;
        int j = idx & 31;
        if (i < j && j < m) {
            float dt = tr_t[i] - tr_t[j];
            float dp = tr_p[i] - tr_p[j];
            if (dt > 0.0f)      c += fmaxf(-dp + 0.1f, 0.0f);
            else if (dt < 0.0f) c += fmaxf( dp + 0.1f, 0.0f);
        }
    }
    c = warp_sum(c);
    if (lane == 0) red[warp] = c;
    __syncthreads();

    // ---- combine, write outputs, reset ticket for replay ----
    if (tid == 0) {
        float rank_total = 0.0f;
        #pragma unroll
        for (int i = 0; i < TPB / 32; i++) rank_total += red[i];
        float eff = sumsq / (float)n_total;
        int n_pairs = m * (m - 1) / 2;
        float rank = (m > 1) ? (rank_total / (float)n_pairs) : 0.0f;
        out[0] = eff + 0.1f * rank;
        if (out_size > 1) out[1] = eff;
        if (out_size > 2) out[2] = rank;
        g_ticket = 0;                   // deterministic graph replay
    }
}

extern "C" void kernel_launch(void* const* d_in, const int* in_sizes, int n_in,
                              void* d_out, int out_size)
{
    const float* pred = (const float*)d_in[0];
    const float* tru  = (const float*)d_in[1];
    float* out = (float*)d_out;

    long long n = (long long)in_sizes[0];   // B * 64 * 64
    int n4 = (int)(n / 4);
    int B  = (int)(n / (64 * 64));

    fused_loss<<<NSTREAM + 1, TPB>>>((const float4*)pred, (const float4*)tru,
                                     out, n4, B, n, out_size);
}